// round 10
// baseline (speedup 1.0000x reference)
#include <cuda_runtime.h>
#include <cstdint>
#include <cstring>

#define BATCH 32
#define TT    512
#define NGATE 1024   // 4*H
#define HDIM  256
#define OUTW  512

// Scratch (static device globals — no allocation allowed)
__device__ float g_xg[(size_t)2 * BATCH * TT * NGATE];   // pre-activations (both dirs)
__device__ float g_h1[(size_t)BATCH * TT * OUTW];        // layer-0 output (fwd||bwd concat)

// ---------------- f32x2 helpers ----------------
__device__ __forceinline__ void ffma2(unsigned long long& d, unsigned long long a, unsigned long long b) {
    asm("fma.rn.f32x2 %0, %1, %2, %0;" : "+l"(d) : "l"(a), "l"(b));
}
__device__ __forceinline__ float fold2(unsigned long long v) {
    float2 f; memcpy(&f, &v, 8); return f.x + f.y;
}
__device__ __forceinline__ unsigned long long pack2(float lo, float hi) {
    unsigned long long u;
    asm("mov.b64 %0, {%1, %2};" : "=l"(u) : "f"(lo), "f"(hi));
    return u;
}

// ---------------------------------------------------------------------------
// Input projection GEMM (unchanged from R5 — passing):
// Tile 128(M) x 64(N) x 32(K-stage), 256 threads, 8m x 4n microtile,
// k-paired FFMA2, register double-buffered gmem prefetch.
// ---------------------------------------------------------------------------
__global__ __launch_bounds__(256, 1) void gemm_proj(
    const float* __restrict__ src, int K, int nst,
    const float* __restrict__ Wf, const float* __restrict__ bf,
    const float* __restrict__ Wb, const float* __restrict__ bb)
{
    const int dir = blockIdx.z;
    const float* __restrict__ W    = dir ? Wb : Wf;
    const float* __restrict__ bias = dir ? bb : bf;
    const int j0 = blockIdx.x * 64;
    const int r0 = blockIdx.y * 128;

    __shared__ __align__(16) float2 As2[2][16][128];
    __shared__ __align__(16) float2 Bs2[2][16][64];

    const int tid = threadIdx.x;

    const int arow  = tid >> 1;
    const int ahalf = tid & 1;
    const int brow  = tid & 63;
    const int bq    = tid >> 6;
    const float* aptr = src + (size_t)(r0 + arow) * K + ahalf * 16;
    const float* bptr = W   + (size_t)(j0 + brow) * K + bq * 8;

    const int wid  = tid >> 5;
    const int lane = tid & 31;
    const int mbase = (wid & 3) * 32 + (lane & 3) * 8;
    const int nbase = (wid >> 2) * 32 + (lane >> 2) * 4;

    unsigned long long acc[8][4];
    #pragma unroll
    for (int i = 0; i < 8; i++)
        #pragma unroll
        for (int u = 0; u < 4; u++) acc[i][u] = 0ull;

    float4 pa[4], pb[2];

    #pragma unroll
    for (int q = 0; q < 4; q++) pa[q] = *(const float4*)(aptr + q * 4);
    #pragma unroll
    for (int q = 0; q < 2; q++) pb[q] = *(const float4*)(bptr + q * 4);

    #pragma unroll
    for (int q = 0; q < 4; q++) {
        int kp = ahalf * 8 + q * 2;
        As2[0][kp    ][arow] = make_float2(pa[q].x, pa[q].y);
        As2[0][kp + 1][arow] = make_float2(pa[q].z, pa[q].w);
    }
    #pragma unroll
    for (int q = 0; q < 2; q++) {
        int kp = bq * 4 + q * 2;
        Bs2[0][kp    ][brow] = make_float2(pb[q].x, pb[q].y);
        Bs2[0][kp + 1][brow] = make_float2(pb[q].z, pb[q].w);
    }
    __syncthreads();

    int buf = 0;
    for (int s = 0; s < nst; ++s) {
        if (s + 1 < nst) {
            const float* ap = aptr + (size_t)(s + 1) * 32;
            const float* bp = bptr + (size_t)(s + 1) * 32;
            #pragma unroll
            for (int q = 0; q < 4; q++) pa[q] = *(const float4*)(ap + q * 4);
            #pragma unroll
            for (int q = 0; q < 2; q++) pb[q] = *(const float4*)(bp + q * 4);
        }

        #pragma unroll
        for (int kp = 0; kp < 16; ++kp) {
            ulonglong2 aA = *(const ulonglong2*)&As2[buf][kp][mbase    ];
            ulonglong2 aB = *(const ulonglong2*)&As2[buf][kp][mbase + 2];
            ulonglong2 aC = *(const ulonglong2*)&As2[buf][kp][mbase + 4];
            ulonglong2 aD = *(const ulonglong2*)&As2[buf][kp][mbase + 6];
            ulonglong2 bA = *(const ulonglong2*)&Bs2[buf][kp][nbase    ];
            ulonglong2 bB = *(const ulonglong2*)&Bs2[buf][kp][nbase + 2];
            unsigned long long av[8] = {aA.x, aA.y, aB.x, aB.y, aC.x, aC.y, aD.x, aD.y};
            unsigned long long bv[4] = {bA.x, bA.y, bB.x, bB.y};
            #pragma unroll
            for (int i = 0; i < 8; i++) {
                ffma2(acc[i][0], av[i], bv[0]);
                ffma2(acc[i][1], av[i], bv[1]);
                ffma2(acc[i][2], av[i], bv[2]);
                ffma2(acc[i][3], av[i], bv[3]);
            }
        }
        __syncthreads();

        if (s + 1 < nst) {
            const int nb = buf ^ 1;
            #pragma unroll
            for (int q = 0; q < 4; q++) {
                int kp = ahalf * 8 + q * 2;
                As2[nb][kp    ][arow] = make_float2(pa[q].x, pa[q].y);
                As2[nb][kp + 1][arow] = make_float2(pa[q].z, pa[q].w);
            }
            #pragma unroll
            for (int q = 0; q < 2; q++) {
                int kp = bq * 4 + q * 2;
                Bs2[nb][kp    ][brow] = make_float2(pb[q].x, pb[q].y);
                Bs2[nb][kp + 1][brow] = make_float2(pb[q].z, pb[q].w);
            }
            __syncthreads();
        }
        buf ^= 1;
    }

    float4 bv4 = *(const float4*)&bias[j0 + nbase];
    #pragma unroll
    for (int i = 0; i < 8; i++) {
        float4 o;
        o.x = fold2(acc[i][0]) + bv4.x;
        o.y = fold2(acc[i][1]) + bv4.y;
        o.z = fold2(acc[i][2]) + bv4.z;
        o.w = fold2(acc[i][3]) + bv4.w;
        *(float4*)(g_xg + ((size_t)dir * (BATCH * TT) + r0 + mbase + i) * NGATE + j0 + nbase) = o;
    }
}

// ---------------------------------------------------------------------------
// Recurrence v7: 512 threads = 128 gates x 4 k-quarters (4 warps/SMSP for
// latency hiding). Wreg 32 ull/thread. 4-way psum reduction.
// Exchange identical to R7 (st.async to 7 peers + STS self-push, 3584B expect).
// ---------------------------------------------------------------------------
__device__ __forceinline__ float sigmoid_fast(float x) {
    return __fdividef(1.f, 1.f + __expf(-x));
}
__device__ __forceinline__ float tanh_fast(float x) {
    float xc = fminf(fmaxf(x, -15.f), 15.f);
    float e = __expf(2.f * xc);
    return __fdividef(e - 1.f, e + 1.f);
}

__global__ __launch_bounds__(512, 1) __cluster_dims__(8, 1, 1)
void lstm_rec(const float* __restrict__ whhF, const float* __restrict__ whhB,
              float* __restrict__ out)
{
    __shared__ __align__(16) float h_s[2 * 1024];   // [2 buf][4 batch][256]
    __shared__ float psum[4][512];                  // [kq][batch*128 + j]
    __shared__ __align__(16) float hstage[128];
    __shared__ __align__(8) unsigned long long full_mbar[2];

    const int tid   = threadIdx.x;       // 0..511
    const int j     = tid & 127;         // gate within CTA slice
    const int kq    = tid >> 7;          // k-quarter 0..3
    const int brank = blockIdx.x & 7;
    const int cid   = blockIdx.x >> 3;
    const int dir   = cid >> 3;
    const int bg    = cid & 7;
    const float* __restrict__ whh = dir ? whhB : whhF;

    const int gate = j >> 5;
    const int kl   = j & 31;
    const int grow = (gate << 8) + (brank << 5) + kl;

    // W slice: 64 k-values = 32 f32x2
    unsigned long long Wreg[32];
    {
        const float* wrow = whh + (size_t)grow * HDIM + (kq << 6);
        #pragma unroll
        for (int q = 0; q < 32; ++q) {
            float2 w = *(const float2*)(wrow + 2 * q);
            memcpy(&Wreg[q], &w, 8);
        }
    }

    uint32_t h_local, m_local;
    asm volatile("{ .reg .u64 t; cvta.to.shared.u64 t, %1; cvt.u32.u64 %0, t; }"
                 : "=r"(h_local) : "l"((const float*)h_s));
    asm volatile("{ .reg .u64 t; cvta.to.shared.u64 t, %1; cvt.u32.u64 %0, t; }"
                 : "=r"(m_local) : "l"((const unsigned long long*)full_mbar));

    // init: count=1 per mbar; expect 3584 B per phase (7 remote peers x 512 B)
    if (tid == 0) {
        asm volatile("mbarrier.init.shared.b64 [%0], %1;" :: "r"(m_local),     "r"(1u) : "memory");
        asm volatile("mbarrier.init.shared.b64 [%0], %1;" :: "r"(m_local + 8), "r"(1u) : "memory");
    }
    for (int idx = tid; idx < 2048; idx += 512) h_s[idx] = 0.f;
    if (tid < 128) hstage[tid] = 0.f;
    __syncthreads();
    if (tid == 0) {
        asm volatile("mbarrier.arrive.expect_tx.shared.b64 _, [%0], %1;"
                     :: "r"(m_local),     "r"(3584u) : "memory");
        asm volatile("mbarrier.arrive.expect_tx.shared.b64 _, [%0], %1;"
                     :: "r"(m_local + 8), "r"(3584u) : "memory");
    }
    __syncthreads();
    asm volatile("barrier.cluster.arrive.aligned;\n\tbarrier.cluster.wait.aligned;" ::: "memory");

    // push mapping (threads 0..255): peer rank = tid>>5
    const int prank = (tid >> 5) & 7;
    uint32_t peer_h = 0, peer_m = 0;
    if (tid < 256) {
        uint32_t rk = (uint32_t)prank;
        asm volatile("mapa.shared::cluster.u32 %0, %1, %2;" : "=r"(peer_h) : "r"(h_local), "r"(rk));
        asm volatile("mapa.shared::cluster.u32 %0, %1, %2;" : "=r"(peer_m) : "r"(m_local), "r"(rk));
    }
    const int i5 = tid & 31;
    const uint32_t push_off = ((uint32_t)(i5 >> 3) << 10) + ((uint32_t)brank << 7) + ((uint32_t)(i5 & 7) << 4);
    const bool pusher = (tid < 256) && (prank != brank);

    // seed buffer 0 with zeros on remote peers (self slice zeroed above)
    if (pusher) {
        const float4 v = *(const float4*)&hstage[i5 << 2];   // zeros
        asm volatile("st.async.shared::cluster.mbarrier::complete_tx::bytes.v4.f32 "
                     "[%0], {%1, %2, %3, %4}, [%5];"
                     :: "r"(peer_h + push_off), "f"(v.x), "f"(v.y), "f"(v.z), "f"(v.w),
                        "r"(peer_m) : "memory");
    }

    const float* xgb = g_xg + (((size_t)dir * BATCH + bg * 4) * TT) * NGATE;

    float c_state = 0.f;
    int t = dir ? (TT - 1) : 0;
    const int tstep = dir ? -1 : 1;

    float x0 = 0.f, x1 = 0.f, x2 = 0.f, x3 = 0.f;
    if (kq == 0) {
        x0 = xgb[((size_t)0 * TT + t) * NGATE + grow];
        x1 = xgb[((size_t)1 * TT + t) * NGATE + grow];
        x2 = xgb[((size_t)2 * TT + t) * NGATE + grow];
        x3 = xgb[((size_t)3 * TT + t) * NGATE + grow];
    }

    int ph0 = 0, ph1 = 0;
    for (int it = 0; it < TT; ++it) {
        const int b = it & 1;
        // ---- wait for this buffer's 3584 tx bytes ----
        {
            const uint32_t mb = m_local + ((uint32_t)b << 3);
            const uint32_t par = (uint32_t)(b ? ph1 : ph0);
            uint32_t done;
            asm volatile(
                "{\n\t.reg .pred p;\n\t"
                "mbarrier.try_wait.parity.acquire.cluster.shared::cta.b64 p, [%1], %2, 0x989680;\n\t"
                "selp.b32 %0, 1, 0, p;\n\t}"
                : "=r"(done) : "r"(mb), "r"(par) : "memory");
            while (!done) {
                asm volatile(
                    "{\n\t.reg .pred p;\n\t"
                    "mbarrier.try_wait.parity.acquire.cluster.shared::cta.b64 p, [%1], %2, 0x989680;\n\t"
                    "selp.b32 %0, 1, 0, p;\n\t}"
                    : "=r"(done) : "r"(mb), "r"(par) : "memory");
            }
            if (b) ph1 ^= 1; else ph0 ^= 1;
            if (tid == 0 && it < TT - 1) {
                asm volatile("mbarrier.arrive.expect_tx.shared.b64 _, [%0], %1;"
                             :: "r"(mb), "r"(3584u) : "memory");
            }
        }

        // early x prefetch for step it+1
        float nx0 = 0.f, nx1 = 0.f, nx2 = 0.f, nx3 = 0.f;
        if (kq == 0 && it + 1 < TT) {
            const int tnx = t + tstep;
            nx0 = xgb[((size_t)0 * TT + tnx) * NGATE + grow];
            nx1 = xgb[((size_t)1 * TT + tnx) * NGATE + grow];
            nx2 = xgb[((size_t)2 * TT + tnx) * NGATE + grow];
            nx3 = xgb[((size_t)3 * TT + tnx) * NGATE + grow];
        }

        unsigned long long acc0, acc1, acc2, acc3;
        if (kq == 0) {
            acc0 = pack2(x0, 0.f); acc1 = pack2(x1, 0.f);
            acc2 = pack2(x2, 0.f); acc3 = pack2(x3, 0.f);
        } else {
            acc0 = acc1 = acc2 = acc3 = 0ull;
        }

        // matvec over this thread's 64-k quarter, 4 batches
        // h_s batch stride = 256 floats = 64 ulonglong2
        const ulonglong2* hptr = reinterpret_cast<const ulonglong2*>(h_s + (b << 10) + (kq << 6));
        #pragma unroll
        for (int q = 0; q < 16; ++q) {
            ulonglong2 ha = hptr[q];
            ulonglong2 hb = hptr[q + 64];
            ulonglong2 hc = hptr[q + 128];
            ulonglong2 hd = hptr[q + 192];
            unsigned long long w0 = Wreg[2 * q], w1 = Wreg[2 * q + 1];
            ffma2(acc0, w0, ha.x); ffma2(acc1, w0, hb.x);
            ffma2(acc2, w0, hc.x); ffma2(acc3, w0, hd.x);
            ffma2(acc0, w1, ha.y); ffma2(acc1, w1, hb.y);
            ffma2(acc2, w1, hc.y); ffma2(acc3, w1, hd.y);
        }

        psum[kq][      j] = fold2(acc0);
        psum[kq][128 + j] = fold2(acc1);
        psum[kq][256 + j] = fold2(acc2);
        psum[kq][384 + j] = fold2(acc3);
        __syncthreads();

        float hval = 0.f;
        if (tid < 128) {
            const int bb   = tid >> 5;
            const int kloc = tid & 31;
            const int base = bb * 128 + kloc;
            float gi = psum[0][base     ] + psum[1][base     ] + psum[2][base     ] + psum[3][base     ];
            float gf = psum[0][base + 32] + psum[1][base + 32] + psum[2][base + 32] + psum[3][base + 32];
            float gg = psum[0][base + 64] + psum[1][base + 64] + psum[2][base + 64] + psum[3][base + 64];
            float go = psum[0][base + 96] + psum[1][base + 96] + psum[2][base + 96] + psum[3][base + 96];
            float i_ = sigmoid_fast(gi);
            float f_ = sigmoid_fast(gf);
            float g_ = tanh_fast(gg);
            float o_ = sigmoid_fast(go);
            c_state = f_ * c_state + i_ * g_;
            hval = o_ * tanh_fast(c_state);
            hstage[tid] = hval;
            // self-push via plain STS (ordered for all warps by the sync below)
            h_s[((b ^ 1) << 10) + bb * 256 + (brank << 5) + kloc] = hval;
        }
        __syncthreads();

        // ---- push h(it) to the 7 REMOTE peers via st.async ----
        if (pusher) {
            const float4 v = *(const float4*)&hstage[i5 << 2];
            const uint32_t dst = peer_h + ((uint32_t)(b ^ 1) << 12) + push_off;
            asm volatile("st.async.shared::cluster.mbarrier::complete_tx::bytes.v4.f32 "
                         "[%0], {%1, %2, %3, %4}, [%5];"
                         :: "r"(dst), "f"(v.x), "f"(v.y), "f"(v.z), "f"(v.w),
                            "r"(peer_m + ((uint32_t)(b ^ 1) << 3)) : "memory");
        }

        // fire-and-forget output store
        if (tid < 128) {
            const int bb   = tid >> 5;
            const int kloc = tid & 31;
            out[(((size_t)(bg * 4 + bb)) * TT + t) * OUTW + (dir << 8) + (brank << 5) + kloc] = hval;
        }

        x0 = nx0; x1 = nx1; x2 = nx2; x3 = nx3;
        t += tstep;
    }

    // consume final incoming pushes so nothing targets this CTA after exit
    {
        const uint32_t mb = m_local;   // buffer 0
        const uint32_t par = (uint32_t)ph0;
        uint32_t done;
        asm volatile(
            "{\n\t.reg .pred p;\n\t"
            "mbarrier.try_wait.parity.acquire.cluster.shared::cta.b64 p, [%1], %2, 0x989680;\n\t"
            "selp.b32 %0, 1, 0, p;\n\t}"
            : "=r"(done) : "r"(mb), "r"(par) : "memory");
        while (!done) {
            asm volatile(
                "{\n\t.reg .pred p;\n\t"
                "mbarrier.try_wait.parity.acquire.cluster.shared::cta.b64 p, [%1], %2, 0x989680;\n\t"
                "selp.b32 %0, 1, 0, p;\n\t}"
                : "=r"(done) : "r"(mb), "r"(par) : "memory");
        }
    }
    asm volatile("barrier.cluster.arrive.aligned;\n\tbarrier.cluster.wait.aligned;" ::: "memory");
}

// ---------------------------------------------------------------------------
extern "C" void kernel_launch(void* const* d_in, const int* in_sizes, int n_in,
                              void* d_out, int out_size)
{
    const float* x         = (const float*)d_in[0];
    const float* w_ih_l0f  = (const float*)d_in[1];
    const float* w_hh_l0f  = (const float*)d_in[2];
    const float* b_l0f     = (const float*)d_in[3];
    const float* w_ih_l0b  = (const float*)d_in[4];
    const float* w_hh_l0b  = (const float*)d_in[5];
    const float* b_l0b     = (const float*)d_in[6];
    const float* w_ih_l1f  = (const float*)d_in[7];
    const float* w_hh_l1f  = (const float*)d_in[8];
    const float* b_l1f     = (const float*)d_in[9];
    const float* w_ih_l1b  = (const float*)d_in[10];
    const float* w_hh_l1b  = (const float*)d_in[11];
    const float* b_l1b     = (const float*)d_in[12];
    float* out = (float*)d_out;

    float* h1 = nullptr;
    cudaGetSymbolAddress((void**)&h1, g_h1);

    dim3 ggrid(16, 128, 2);   // N/64, M/128, dirs

    // Layer 0 (K=256, 8 stages)
    gemm_proj<<<ggrid, 256>>>(x, 256, 8, w_ih_l0f, b_l0f, w_ih_l0b, b_l0b);
    lstm_rec<<<128, 512>>>(w_hh_l0f, w_hh_l0b, h1);

    // Layer 1 (K=512, 16 stages)
    gemm_proj<<<ggrid, 256>>>(h1, 512, 16, w_ih_l1f, b_l1f, w_ih_l1b, b_l1b);
    lstm_rec<<<128, 512>>>(w_hh_l1f, w_hh_l1b, out);
}

// round 12
// speedup vs baseline: 1.2028x; 1.2028x over previous
#include <cuda_runtime.h>
#include <cstdint>
#include <cstring>

#define BATCH 32
#define TT    512
#define NGATE 1024   // 4*H
#define HDIM  256
#define OUTW  512

// Scratch (static device globals — no allocation allowed)
__device__ float g_xg[(size_t)2 * BATCH * TT * NGATE];   // pre-activations (both dirs)
__device__ float g_h1[(size_t)BATCH * TT * OUTW];        // layer-0 output (fwd||bwd concat)

// ---------------- f32x2 helpers (recurrence) ----------------
__device__ __forceinline__ void ffma2(unsigned long long& d, unsigned long long a, unsigned long long b) {
    asm("fma.rn.f32x2 %0, %1, %2, %0;" : "+l"(d) : "l"(a), "l"(b));
}
__device__ __forceinline__ float fold2(unsigned long long v) {
    float2 f; memcpy(&f, &v, 8); return f.x + f.y;
}
__device__ __forceinline__ unsigned long long pack2(float lo, float hi) {
    unsigned long long u;
    asm("mov.b64 %0, {%1, %2};" : "=l"(u) : "f"(lo), "f"(hi));
    return u;
}

// ===========================================================================
// 3xTF32 mma.sync GEMM:  xg[dir][r][j] = src[r][:] . W[dir][j][:] + bias[j]
// (portable PTX — compute_103-safe; no tcgen05)
// CTA tile M=128 x N=64, K-stage 16. 8 warps: 4(M) x 2(N), warp tile 32x32.
// D = xh*Wh + xh*Wl + xl*Wh  (fp32-grade accuracy via tf32 split)
// ===========================================================================
__device__ __forceinline__ uint32_t to_tf32(float x) {
    uint32_t r;
    asm("cvt.rna.tf32.f32 %0, %1;" : "=r"(r) : "f"(x));
    return r;
}
__device__ __forceinline__ void mma_tf32(float c[4],
    uint32_t a0, uint32_t a1, uint32_t a2, uint32_t a3,
    uint32_t b0, uint32_t b1)
{
    asm("mma.sync.aligned.m16n8k8.row.col.f32.tf32.tf32.f32 "
        "{%0,%1,%2,%3}, {%4,%5,%6,%7}, {%8,%9}, {%0,%1,%2,%3};"
        : "+f"(c[0]), "+f"(c[1]), "+f"(c[2]), "+f"(c[3])
        : "r"(a0), "r"(a1), "r"(a2), "r"(a3), "r"(b0), "r"(b1));
}

// smem layout (uint32 units): Ah[2][16][132], Al[2][16][132], Bh[2][16][68], Bl[2][16][68]
#define SA_AH 0
#define SA_AL 4224
#define SA_BH 8448
#define SA_BL 10624
#define SA_TOTAL 12800   // uint32 -> 51200 bytes dynamic smem

__global__ __launch_bounds__(256, 1) void gemm_tc32(
    const float* __restrict__ src, int K, int nst,
    const float* __restrict__ Wf, const float* __restrict__ bf,
    const float* __restrict__ Wb, const float* __restrict__ bb)
{
    extern __shared__ __align__(16) uint32_t sm[];
    const int dir = blockIdx.z;
    const float* __restrict__ W    = dir ? Wb : Wf;
    const float* __restrict__ bias = dir ? bb : bf;
    const int j0 = blockIdx.x * 64;
    const int r0 = blockIdx.y * 128;

    const int tid  = threadIdx.x;
    const int wid  = tid >> 5;
    const int lane = tid & 31;
    const int g    = lane >> 2;      // group 0..7
    const int tg   = lane & 3;       // thread-in-group 0..3
    const int mrow = (wid & 3) * 32; // warp M offset
    const int ncol = (wid >> 2) * 32;// warp N offset

    // loaders
    const int arow  = tid >> 1;          // 0..127
    const int ahalf = tid & 1;           // k half (8 floats)
    const int brow  = tid >> 2;          // 0..63
    const int bq4   = (tid & 3) * 4;     // k quad (4 floats)
    const float* aptr = src + (size_t)(r0 + arow) * K + ahalf * 8;
    const float* bptr = W   + (size_t)(j0 + brow) * K + bq4;

    float c[2][4][4];
    #pragma unroll
    for (int i = 0; i < 2; i++)
        #pragma unroll
        for (int jn = 0; jn < 4; jn++)
            #pragma unroll
            for (int u = 0; u < 4; u++) c[i][jn][u] = 0.f;

    float apf[8]; float bpf[4];
    auto ldg_stage = [&](int s) {
        float4 v0 = *(const float4*)(aptr + s * 16);
        float4 v1 = *(const float4*)(aptr + s * 16 + 4);
        apf[0]=v0.x; apf[1]=v0.y; apf[2]=v0.z; apf[3]=v0.w;
        apf[4]=v1.x; apf[5]=v1.y; apf[6]=v1.z; apf[7]=v1.w;
        float4 w0 = *(const float4*)(bptr + s * 16);
        bpf[0]=w0.x; bpf[1]=w0.y; bpf[2]=w0.z; bpf[3]=w0.w;
    };
    auto sts_stage = [&](int buf) {
        uint32_t* ah = sm + SA_AH + buf * 2112;
        uint32_t* al = sm + SA_AL + buf * 2112;
        #pragma unroll
        for (int q = 0; q < 8; q++) {
            int k = ahalf * 8 + q;
            uint32_t hi = to_tf32(apf[q]);
            uint32_t lo = to_tf32(apf[q] - __uint_as_float(hi));
            ah[k * 132 + arow] = hi;
            al[k * 132 + arow] = lo;
        }
        uint32_t* bh = sm + SA_BH + buf * 1088;
        uint32_t* bl = sm + SA_BL + buf * 1088;
        #pragma unroll
        for (int q = 0; q < 4; q++) {
            int k = bq4 + q;
            uint32_t hi = to_tf32(bpf[q]);
            uint32_t lo = to_tf32(bpf[q] - __uint_as_float(hi));
            bh[k * 68 + brow] = hi;
            bl[k * 68 + brow] = lo;
        }
    };
    auto compute_stage = [&](int buf) {
        const uint32_t* ah = sm + SA_AH + buf * 2112;
        const uint32_t* al = sm + SA_AL + buf * 2112;
        const uint32_t* bh = sm + SA_BH + buf * 1088;
        const uint32_t* bl = sm + SA_BL + buf * 1088;
        #pragma unroll
        for (int kb = 0; kb < 2; kb++) {
            const int k0 = kb * 8 + tg;
            const int k1 = k0 + 4;
            uint32_t fah[2][4], fal[2][4], fbh[4][2], fbl[4][2];
            #pragma unroll
            for (int i = 0; i < 2; i++) {
                const int r = mrow + i * 16 + g;
                fah[i][0] = ah[k0 * 132 + r];
                fah[i][1] = ah[k0 * 132 + r + 8];
                fah[i][2] = ah[k1 * 132 + r];
                fah[i][3] = ah[k1 * 132 + r + 8];
                fal[i][0] = al[k0 * 132 + r];
                fal[i][1] = al[k0 * 132 + r + 8];
                fal[i][2] = al[k1 * 132 + r];
                fal[i][3] = al[k1 * 132 + r + 8];
            }
            #pragma unroll
            for (int jn = 0; jn < 4; jn++) {
                const int cc = ncol + jn * 8 + g;
                fbh[jn][0] = bh[k0 * 68 + cc];
                fbh[jn][1] = bh[k1 * 68 + cc];
                fbl[jn][0] = bl[k0 * 68 + cc];
                fbl[jn][1] = bl[k1 * 68 + cc];
            }
            #pragma unroll
            for (int i = 0; i < 2; i++)
                #pragma unroll
                for (int jn = 0; jn < 4; jn++) {
                    mma_tf32(c[i][jn], fah[i][0], fah[i][1], fah[i][2], fah[i][3], fbh[jn][0], fbh[jn][1]);
                    mma_tf32(c[i][jn], fah[i][0], fah[i][1], fah[i][2], fah[i][3], fbl[jn][0], fbl[jn][1]);
                    mma_tf32(c[i][jn], fal[i][0], fal[i][1], fal[i][2], fal[i][3], fbh[jn][0], fbh[jn][1]);
                }
        }
    };

    // pipeline: 1 sync per stage, double-buffered
    ldg_stage(0);
    sts_stage(0);
    __syncthreads();
    for (int s = 0; s < nst; ++s) {
        if (s + 1 < nst) ldg_stage(s + 1);
        compute_stage(s & 1);
        if (s + 1 < nst) sts_stage((s + 1) & 1);
        __syncthreads();
    }

    // epilogue: +bias, direct float2 stores
    float* outp = g_xg + ((size_t)dir * (BATCH * TT)) * NGATE;
    #pragma unroll
    for (int i = 0; i < 2; i++) {
        #pragma unroll
        for (int jn = 0; jn < 4; jn++) {
            const int col = j0 + ncol + jn * 8 + 2 * tg;
            const float b0v = __ldg(&bias[col]);
            const float b1v = __ldg(&bias[col + 1]);
            const int row = r0 + mrow + i * 16 + g;
            float2 v0 = make_float2(c[i][jn][0] + b0v, c[i][jn][1] + b1v);
            float2 v1 = make_float2(c[i][jn][2] + b0v, c[i][jn][3] + b1v);
            *(float2*)&outp[(size_t)row * NGATE + col] = v0;
            *(float2*)&outp[(size_t)(row + 8) * NGATE + col] = v1;
        }
    }
}

// ---------------------------------------------------------------------------
// Recurrence (EXACT R7 best — 5049us): st.async + tx-count mbarrier.
// ---------------------------------------------------------------------------
__device__ __forceinline__ float sigmoid_fast(float x) {
    return __fdividef(1.f, 1.f + __expf(-x));
}
__device__ __forceinline__ float tanh_fast(float x) {
    float xc = fminf(fmaxf(x, -15.f), 15.f);
    float e = __expf(2.f * xc);
    return __fdividef(e - 1.f, e + 1.f);
}

__global__ __launch_bounds__(256, 1) __cluster_dims__(8, 1, 1)
void lstm_rec(const float* __restrict__ whhF, const float* __restrict__ whhB,
              float* __restrict__ out)
{
    __shared__ __align__(16) float h_s[2 * 1024];   // [2 buf][4 batch][256]
    __shared__ float g_s [512];
    __shared__ float rsum[512];
    __shared__ __align__(16) float hstage[128];
    __shared__ __align__(8) unsigned long long full_mbar[2];

    const int tid   = threadIdx.x;
    const int j     = tid & 127;
    const int kh    = tid >> 7;
    const int brank = blockIdx.x & 7;
    const int cid   = blockIdx.x >> 3;
    const int dir   = cid >> 3;
    const int bg    = cid & 7;
    const float* __restrict__ whh = dir ? whhB : whhF;

    const int gate = j >> 5;
    const int kl   = j & 31;
    const int grow = (gate << 8) + (brank << 5) + kl;

    unsigned long long Wreg[64];
    {
        const float* wrow = whh + (size_t)grow * HDIM + (kh << 7);
        #pragma unroll
        for (int q = 0; q < 64; ++q) {
            float2 w = *(const float2*)(wrow + 2 * q);
            memcpy(&Wreg[q], &w, 8);
        }
    }

    uint32_t h_local, m_local;
    asm volatile("{ .reg .u64 t; cvta.to.shared.u64 t, %1; cvt.u32.u64 %0, t; }"
                 : "=r"(h_local) : "l"((const float*)h_s));
    asm volatile("{ .reg .u64 t; cvta.to.shared.u64 t, %1; cvt.u32.u64 %0, t; }"
                 : "=r"(m_local) : "l"((const unsigned long long*)full_mbar));

    if (tid == 0) {
        asm volatile("mbarrier.init.shared.b64 [%0], %1;" :: "r"(m_local),     "r"(1u) : "memory");
        asm volatile("mbarrier.init.shared.b64 [%0], %1;" :: "r"(m_local + 8), "r"(1u) : "memory");
    }
    if (tid < 128) hstage[tid] = 0.f;
    __syncthreads();
    if (tid == 0) {
        asm volatile("mbarrier.arrive.expect_tx.shared.b64 _, [%0], %1;"
                     :: "r"(m_local),     "r"(4096u) : "memory");
        asm volatile("mbarrier.arrive.expect_tx.shared.b64 _, [%0], %1;"
                     :: "r"(m_local + 8), "r"(4096u) : "memory");
    }
    __syncthreads();
    asm volatile("barrier.cluster.arrive.aligned;\n\tbarrier.cluster.wait.aligned;" ::: "memory");

    uint32_t peer_h, peer_m;
    {
        uint32_t rk = (uint32_t)(tid >> 5);
        asm volatile("mapa.shared::cluster.u32 %0, %1, %2;" : "=r"(peer_h) : "r"(h_local), "r"(rk));
        asm volatile("mapa.shared::cluster.u32 %0, %1, %2;" : "=r"(peer_m) : "r"(m_local), "r"(rk));
    }
    const int i5 = tid & 31;
    const uint32_t push_off = ((uint32_t)(i5 >> 3) << 10) + ((uint32_t)brank << 7) + ((uint32_t)(i5 & 7) << 4);

    {
        const float4 v = *(const float4*)&hstage[i5 << 2];   // zeros
        asm volatile("st.async.shared::cluster.mbarrier::complete_tx::bytes.v4.f32 "
                     "[%0], {%1, %2, %3, %4}, [%5];"
                     :: "r"(peer_h + push_off), "f"(v.x), "f"(v.y), "f"(v.z), "f"(v.w),
                        "r"(peer_m) : "memory");
    }

    const float* xgb = g_xg + (((size_t)dir * BATCH + bg * 4) * TT) * NGATE;

    float c_state = 0.f;
    int t = dir ? (TT - 1) : 0;
    const int tstep = dir ? -1 : 1;

    float x0 = 0.f, x1 = 0.f, x2 = 0.f, x3 = 0.f;
    if (kh == 0) {
        x0 = xgb[((size_t)0 * TT + t) * NGATE + grow];
        x1 = xgb[((size_t)1 * TT + t) * NGATE + grow];
        x2 = xgb[((size_t)2 * TT + t) * NGATE + grow];
        x3 = xgb[((size_t)3 * TT + t) * NGATE + grow];
    }

    int ph0 = 0, ph1 = 0;
    for (int it = 0; it < TT; ++it) {
        const int b = it & 1;
        {
            const uint32_t mb = m_local + ((uint32_t)b << 3);
            const uint32_t par = (uint32_t)(b ? ph1 : ph0);
            uint32_t done;
            asm volatile(
                "{\n\t.reg .pred p;\n\t"
                "mbarrier.try_wait.parity.acquire.cluster.shared::cta.b64 p, [%1], %2, 0x989680;\n\t"
                "selp.b32 %0, 1, 0, p;\n\t}"
                : "=r"(done) : "r"(mb), "r"(par) : "memory");
            while (!done) {
                asm volatile(
                    "{\n\t.reg .pred p;\n\t"
                    "mbarrier.try_wait.parity.acquire.cluster.shared::cta.b64 p, [%1], %2, 0x989680;\n\t"
                    "selp.b32 %0, 1, 0, p;\n\t}"
                    : "=r"(done) : "r"(mb), "r"(par) : "memory");
            }
            if (b) ph1 ^= 1; else ph0 ^= 1;
            if (tid == 0 && it < TT - 1) {
                asm volatile("mbarrier.arrive.expect_tx.shared.b64 _, [%0], %1;"
                             :: "r"(mb), "r"(4096u) : "memory");
            }
        }

        unsigned long long acc0, acc1, acc2, acc3;
        if (kh == 0) {
            acc0 = pack2(x0, 0.f); acc1 = pack2(x1, 0.f);
            acc2 = pack2(x2, 0.f); acc3 = pack2(x3, 0.f);
        } else {
            acc0 = acc1 = acc2 = acc3 = 0ull;
        }

        const ulonglong2* hptr = reinterpret_cast<const ulonglong2*>(h_s + (b << 10) + (kh << 7));
        #pragma unroll
        for (int q = 0; q < 32; ++q) {
            ulonglong2 ha = hptr[q];
            ulonglong2 hb = hptr[q + 64];
            ulonglong2 hc = hptr[q + 128];
            ulonglong2 hd = hptr[q + 192];
            unsigned long long w0 = Wreg[2 * q], w1 = Wreg[2 * q + 1];
            ffma2(acc0, w0, ha.x); ffma2(acc1, w0, hb.x);
            ffma2(acc2, w0, hc.x); ffma2(acc3, w0, hd.x);
            ffma2(acc0, w1, ha.y); ffma2(acc1, w1, hb.y);
            ffma2(acc2, w1, hc.y); ffma2(acc3, w1, hd.y);
        }

        float s0 = fold2(acc0), s1 = fold2(acc1), s2 = fold2(acc2), s3 = fold2(acc3);
        if (kh == 0) {
            g_s[      j] = s0; g_s[128 + j] = s1; g_s[256 + j] = s2; g_s[384 + j] = s3;
        } else {
            rsum[      j] = s0; rsum[128 + j] = s1; rsum[256 + j] = s2; rsum[384 + j] = s3;
        }
        __syncthreads();

        float hval = 0.f;
        if (tid < 128) {
            const int bb   = tid >> 5;
            const int kloc = tid & 31;
            const int base = bb * 128 + kloc;
            float gi = g_s[base     ] + rsum[base     ];
            float gf = g_s[base + 32] + rsum[base + 32];
            float gg = g_s[base + 64] + rsum[base + 64];
            float go = g_s[base + 96] + rsum[base + 96];
            float i_ = sigmoid_fast(gi);
            float f_ = sigmoid_fast(gf);
            float g_ = tanh_fast(gg);
            float o_ = sigmoid_fast(go);
            c_state = f_ * c_state + i_ * g_;
            hval = o_ * tanh_fast(c_state);
            hstage[tid] = hval;
        }
        __syncthreads();

        {
            const float4 v = *(const float4*)&hstage[i5 << 2];
            const uint32_t dst = peer_h + ((uint32_t)(b ^ 1) << 12) + push_off;
            asm volatile("st.async.shared::cluster.mbarrier::complete_tx::bytes.v4.f32 "
                         "[%0], {%1, %2, %3, %4}, [%5];"
                         :: "r"(dst), "f"(v.x), "f"(v.y), "f"(v.z), "f"(v.w),
                            "r"(peer_m + ((uint32_t)(b ^ 1) << 3)) : "memory");
        }

        if (tid < 128) {
            const int bb   = tid >> 5;
            const int kloc = tid & 31;
            out[(((size_t)(bg * 4 + bb)) * TT + t) * OUTW + (dir << 8) + (brank << 5) + kloc] = hval;
        }
        if (kh == 0 && it + 1 < TT) {
            const int tnx = t + tstep;
            x0 = xgb[((size_t)0 * TT + tnx) * NGATE + grow];
            x1 = xgb[((size_t)1 * TT + tnx) * NGATE + grow];
            x2 = xgb[((size_t)2 * TT + tnx) * NGATE + grow];
            x3 = xgb[((size_t)3 * TT + tnx) * NGATE + grow];
        }

        t += tstep;
    }

    {
        const uint32_t mb = m_local;
        const uint32_t par = (uint32_t)ph0;
        uint32_t done;
        asm volatile(
            "{\n\t.reg .pred p;\n\t"
            "mbarrier.try_wait.parity.acquire.cluster.shared::cta.b64 p, [%1], %2, 0x989680;\n\t"
            "selp.b32 %0, 1, 0, p;\n\t}"
            : "=r"(done) : "r"(mb), "r"(par) : "memory");
        while (!done) {
            asm volatile(
                "{\n\t.reg .pred p;\n\t"
                "mbarrier.try_wait.parity.acquire.cluster.shared::cta.b64 p, [%1], %2, 0x989680;\n\t"
                "selp.b32 %0, 1, 0, p;\n\t}"
                : "=r"(done) : "r"(mb), "r"(par) : "memory");
        }
    }
    asm volatile("barrier.cluster.arrive.aligned;\n\tbarrier.cluster.wait.aligned;" ::: "memory");
}

// ---------------------------------------------------------------------------
extern "C" void kernel_launch(void* const* d_in, const int* in_sizes, int n_in,
                              void* d_out, int out_size)
{
    const float* x         = (const float*)d_in[0];
    const float* w_ih_l0f  = (const float*)d_in[1];
    const float* w_hh_l0f  = (const float*)d_in[2];
    const float* b_l0f     = (const float*)d_in[3];
    const float* w_ih_l0b  = (const float*)d_in[4];
    const float* w_hh_l0b  = (const float*)d_in[5];
    const float* b_l0b     = (const float*)d_in[6];
    const float* w_ih_l1f  = (const float*)d_in[7];
    const float* w_hh_l1f  = (const float*)d_in[8];
    const float* b_l1f     = (const float*)d_in[9];
    const float* w_ih_l1b  = (const float*)d_in[10];
    const float* w_hh_l1b  = (const float*)d_in[11];
    const float* b_l1b     = (const float*)d_in[12];
    float* out = (float*)d_out;

    float* h1 = nullptr;
    cudaGetSymbolAddress((void**)&h1, g_h1);

    const int smemB = SA_TOTAL * 4;   // 51200 B
    cudaFuncSetAttribute(gemm_tc32, cudaFuncAttributeMaxDynamicSharedMemorySize, smemB);

    dim3 tgrid(16, 128, 2);   // N/64, M/128, dirs

    // Layer 0 (K=256, 16 stages of 16)
    gemm_tc32<<<tgrid, 256, smemB>>>(x, 256, 16, w_ih_l0f, b_l0f, w_ih_l0b, b_l0b);
    lstm_rec<<<128, 256>>>(w_hh_l0f, w_hh_l0b, h1);

    // Layer 1 (K=512, 32 stages of 16)
    gemm_tc32<<<tgrid, 256, smemB>>>(h1, 512, 32, w_ih_l1f, b_l1f, w_ih_l1b, b_l1b);
    lstm_rec<<<128, 256>>>(w_hh_l1f, w_hh_l1b, out);
}